// round 1
// baseline (speedup 1.0000x reference)
#include <cuda_runtime.h>
#include <math.h>

// ---------------- problem constants ----------------
#define BATCH 16
#define TOK   1280           // T = 1024 img + 256 rad
#define CH    512            // C
#define NHEAD 8
#define HDIM  64
#define NLAYER 6
#define FFDIM 2048
#define MROWS (BATCH*TOK)    // 20480

// ---------------- device scratch (no allocation allowed) ----------------
__device__ float g_x [MROWS*CH];
__device__ float g_h [MROWS*CH];
__device__ float g_q [MROWS*CH];
__device__ float g_k [MROWS*CH];
__device__ float g_v [MROWS*CH];
__device__ float g_y [MROWS*CH];
__device__ float g_ff[MROWS*FFDIM];

// ---------------- embed: (B,C,H,W) -> (B,T,C) + pos_emb ----------------
__global__ void embed_kernel(const float* __restrict__ img,
                             const float* __restrict__ rad,
                             const float* __restrict__ pos)
{
    int idx = blockIdx.x * blockDim.x + threadIdx.x;   // over MROWS*CH
    int c   = idx & (CH - 1);
    int row = idx >> 9;
    int b   = row / TOK;
    int t   = row - b * TOK;
    float v;
    if (t < 1024) v = img[(size_t)(b * CH + c) * 1024 + t];
    else          v = rad[(size_t)(b * CH + c) * 256  + (t - 1024)];
    g_x[idx] = v + pos[t * CH + c];
}

// ---------------- layernorm: one warp per 512-wide row ----------------
__global__ void ln_kernel(const float* __restrict__ x, float* __restrict__ o,
                          const float* __restrict__ w, const float* __restrict__ bb)
{
    int warp = threadIdx.x >> 5, lane = threadIdx.x & 31;
    int row  = blockIdx.x * 8 + warp;
    const float4* xr = (const float4*)(x + (size_t)row * CH);
    float4 v[4];
    float s = 0.f, s2 = 0.f;
#pragma unroll
    for (int i = 0; i < 4; i++) {
        v[i] = xr[lane + 32 * i];
        s  += v[i].x + v[i].y + v[i].z + v[i].w;
        s2 += v[i].x*v[i].x + v[i].y*v[i].y + v[i].z*v[i].z + v[i].w*v[i].w;
    }
#pragma unroll
    for (int off = 16; off; off >>= 1) {
        s  += __shfl_xor_sync(0xffffffffu, s,  off);
        s2 += __shfl_xor_sync(0xffffffffu, s2, off);
    }
    float m   = s * (1.f / CH);
    float inv = rsqrtf(s2 * (1.f / CH) - m * m + 1e-5f);
    const float4* wr = (const float4*)w;
    const float4* br = (const float4*)bb;
    float4* orow = (float4*)(o + (size_t)row * CH);
#pragma unroll
    for (int i = 0; i < 4; i++) {
        float4 wv = wr[lane + 32 * i], bv = br[lane + 32 * i], ov;
        ov.x = (v[i].x - m) * inv * wv.x + bv.x;
        ov.y = (v[i].y - m) * inv * wv.y + bv.y;
        ov.z = (v[i].z - m) * inv * wv.z + bv.z;
        ov.w = (v[i].w - m) * inv * wv.w + bv.w;
        orow[lane + 32 * i] = ov;
    }
}

// ---------------- final LN + scatter to (img_out, rad_out) layout ----------------
__global__ void lnf_kernel(const float* __restrict__ x, float* __restrict__ out,
                           const float* __restrict__ w, const float* __restrict__ bb)
{
    int warp = threadIdx.x >> 5, lane = threadIdx.x & 31;
    int row  = blockIdx.x * 8 + warp;
    const float4* xr = (const float4*)(x + (size_t)row * CH);
    float4 v[4];
    float s = 0.f, s2 = 0.f;
#pragma unroll
    for (int i = 0; i < 4; i++) {
        v[i] = xr[lane + 32 * i];
        s  += v[i].x + v[i].y + v[i].z + v[i].w;
        s2 += v[i].x*v[i].x + v[i].y*v[i].y + v[i].z*v[i].z + v[i].w*v[i].w;
    }
#pragma unroll
    for (int off = 16; off; off >>= 1) {
        s  += __shfl_xor_sync(0xffffffffu, s,  off);
        s2 += __shfl_xor_sync(0xffffffffu, s2, off);
    }
    float m   = s * (1.f / CH);
    float inv = rsqrtf(s2 * (1.f / CH) - m * m + 1e-5f);
    int b = row / TOK, t = row - b * TOK;
    float* dst;
    if (t < 1024) dst = out + ((size_t)b * 1024 + t) * CH;                    // img block
    else          dst = out + (size_t)BATCH*1024*CH + ((size_t)b*256 + (t-1024))*CH; // rad block
    const float4* wr = (const float4*)w;
    const float4* br = (const float4*)bb;
    float4* orow = (float4*)dst;
#pragma unroll
    for (int i = 0; i < 4; i++) {
        float4 wv = wr[lane + 32 * i], bv = br[lane + 32 * i], ov;
        ov.x = (v[i].x - m) * inv * wv.x + bv.x;
        ov.y = (v[i].y - m) * inv * wv.y + bv.y;
        ov.z = (v[i].z - m) * inv * wv.z + bv.z;
        ov.w = (v[i].w - m) * inv * wv.w + bv.w;
        orow[lane + 32 * i] = ov;
    }
}

// ---------------- fp32 tiled GEMM: out = act(A[M,K]@B[K,N] + bias) (+res) ----------------
// 64x64 tile, BK=16, 256 threads, 4x4 per-thread microtile.
template<int ACT, bool RES>
__global__ void __launch_bounds__(256) gemm_kernel(
    const float* __restrict__ A, const float* __restrict__ Bm,
    const float* __restrict__ bias, const float* __restrict__ res,
    float* __restrict__ out, int N, int K)
{
    __shared__ float As[16][68];   // [k][m] (transposed)
    __shared__ float Bs[16][68];   // [k][n]
    const int tid = threadIdx.x;
    const int tx = tid & 15, ty = tid >> 4;
    const int m0 = blockIdx.y * 64, n0 = blockIdx.x * 64;

    const int arow = tid >> 2, ak4 = (tid & 3) * 4;
    const int brow = tid >> 4, bc4 = (tid & 15) * 4;

    float acc[4][4];
#pragma unroll
    for (int i = 0; i < 4; i++)
#pragma unroll
        for (int j = 0; j < 4; j++) acc[i][j] = 0.f;

    for (int k0 = 0; k0 < K; k0 += 16) {
        float4 av = *(const float4*)(A + (size_t)(m0 + arow) * K + k0 + ak4);
        As[ak4 + 0][arow] = av.x;
        As[ak4 + 1][arow] = av.y;
        As[ak4 + 2][arow] = av.z;
        As[ak4 + 3][arow] = av.w;
        *(float4*)&Bs[brow][bc4] =
            *(const float4*)(Bm + (size_t)(k0 + brow) * N + n0 + bc4);
        __syncthreads();
#pragma unroll
        for (int kk = 0; kk < 16; kk++) {
            float4 a4 = *(const float4*)&As[kk][ty * 4];
            float4 b4 = *(const float4*)&Bs[kk][tx * 4];
            float ar[4] = {a4.x, a4.y, a4.z, a4.w};
            float br[4] = {b4.x, b4.y, b4.z, b4.w};
#pragma unroll
            for (int i = 0; i < 4; i++)
#pragma unroll
                for (int j = 0; j < 4; j++)
                    acc[i][j] = fmaf(ar[i], br[j], acc[i][j]);
        }
        __syncthreads();
    }

    float4 bv = *(const float4*)(bias + n0 + tx * 4);
    float bb[4] = {bv.x, bv.y, bv.z, bv.w};
#pragma unroll
    for (int i = 0; i < 4; i++) {
        int row = m0 + ty * 4 + i;
        float vv[4];
#pragma unroll
        for (int j = 0; j < 4; j++) {
            vv[j] = acc[i][j] + bb[j];
            if (ACT == 1) vv[j] = fmaxf(vv[j], 0.f);
        }
        if (RES) {
            float4 rv = *(const float4*)(res + (size_t)row * N + n0 + tx * 4);
            vv[0] += rv.x; vv[1] += rv.y; vv[2] += rv.z; vv[3] += rv.w;
        }
        float4 ov; ov.x = vv[0]; ov.y = vv[1]; ov.z = vv[2]; ov.w = vv[3];
        *(float4*)(out + (size_t)row * N + n0 + tx * 4) = ov;
    }
}

// ---------------- fused flash-style attention ----------------
// grid (20, NH, B). 64-row Q tile, 20 K/V tiles of 64. Online softmax.
#define ATTN_SMEM_FLOATS (4 * 64 * 68 + 3 * 64)
#define ATTN_SMEM_BYTES  (ATTN_SMEM_FLOATS * 4)

__global__ void __launch_bounds__(256) attn_kernel(
    const float* __restrict__ Qg, const float* __restrict__ Kg,
    const float* __restrict__ Vg, float* __restrict__ Yg)
{
    extern __shared__ float sm[];
    float (*Qs)[68] = (float(*)[68])(sm);              // [d][i]
    float (*Ks)[68] = (float(*)[68])(sm + 64 * 68);    // [d][j]
    float (*Vs)[68] = (float(*)[68])(sm + 2 * 64 * 68);// [kk][j]
    float (*Ps)[68] = (float(*)[68])(sm + 3 * 64 * 68);// [kk][i]
    float* mrow = sm + 4 * 64 * 68;
    float* lrow = mrow + 64;
    float* arow = lrow + 64;

    const int q0 = blockIdx.x * 64;
    const int h  = blockIdx.y;
    const int bz = blockIdx.z;
    const int tid = threadIdx.x;
    const int tx = tid & 15, ty = tid >> 4;
    const size_t base = (size_t)bz * TOK * CH + h * HDIM;

    // load Q tile (transposed, pre-scaled by 1/sqrt(HD))
    {
        int i = tid >> 2;
#pragma unroll
        for (int rep = 0; rep < 4; rep++) {
            int d0 = (tid & 3) * 4 + rep * 16;
            float4 qv = *(const float4*)(Qg + base + (size_t)(q0 + i) * CH + d0);
            Qs[d0 + 0][i] = qv.x * 0.125f;
            Qs[d0 + 1][i] = qv.y * 0.125f;
            Qs[d0 + 2][i] = qv.z * 0.125f;
            Qs[d0 + 3][i] = qv.w * 0.125f;
        }
    }
    if (tid < 64) { mrow[tid] = -1e30f; lrow[tid] = 0.f; }

    float acc[4][4];
#pragma unroll
    for (int i = 0; i < 4; i++)
#pragma unroll
        for (int j = 0; j < 4; j++) acc[i][j] = 0.f;

    for (int kt = 0; kt < 20; kt++) {
        __syncthreads();               // prev iter's consumers done before overwrite
        int k0 = kt * 64;
        {
            int j = tid >> 2;
#pragma unroll
            for (int rep = 0; rep < 4; rep++) {
                int d0 = (tid & 3) * 4 + rep * 16;
                float4 kv = *(const float4*)(Kg + base + (size_t)(k0 + j) * CH + d0);
                Ks[d0 + 0][j] = kv.x;
                Ks[d0 + 1][j] = kv.y;
                Ks[d0 + 2][j] = kv.z;
                Ks[d0 + 3][j] = kv.w;
                float4 vv = *(const float4*)(Vg + base + (size_t)(k0 + j) * CH + d0);
                *(float4*)&Vs[j][d0] = vv;
            }
        }
        __syncthreads();

        // S = Q @ K^T  (4x4 fragment per thread)
        float s[4][4];
#pragma unroll
        for (int i = 0; i < 4; i++)
#pragma unroll
            for (int j = 0; j < 4; j++) s[i][j] = 0.f;
#pragma unroll 8
        for (int d = 0; d < 64; d++) {
            float4 qa = *(const float4*)&Qs[d][ty * 4];
            float4 kb = *(const float4*)&Ks[d][tx * 4];
            float qr[4] = {qa.x, qa.y, qa.z, qa.w};
            float kr[4] = {kb.x, kb.y, kb.z, kb.w};
#pragma unroll
            for (int i = 0; i < 4; i++)
#pragma unroll
                for (int j = 0; j < 4; j++)
                    s[i][j] = fmaf(qr[i], kr[j], s[i][j]);
        }
        // store transposed: Ps[kk][i]
#pragma unroll
        for (int i = 0; i < 4; i++)
#pragma unroll
            for (int j = 0; j < 4; j++)
                Ps[tx * 4 + j][ty * 4 + i] = s[i][j];
        __syncthreads();

        // online softmax per row (64 threads, one row each)
        if (tid < 64) {
            int i = tid;
            float mold = mrow[i];
            float m = mold;
#pragma unroll 8
            for (int kk = 0; kk < 64; kk++) m = fmaxf(m, Ps[kk][i]);
            float al = __expf(mold - m);
            float ssum = 0.f;
#pragma unroll 8
            for (int kk = 0; kk < 64; kk++) {
                float p = __expf(Ps[kk][i] - m);
                Ps[kk][i] = p;
                ssum += p;
            }
            lrow[i] = lrow[i] * al + ssum;
            mrow[i] = m;
            arow[i] = al;
        }
        __syncthreads();

        // O = O*alpha + P @ V
        float a0 = arow[ty * 4 + 0], a1 = arow[ty * 4 + 1];
        float a2 = arow[ty * 4 + 2], a3 = arow[ty * 4 + 3];
#pragma unroll
        for (int j = 0; j < 4; j++) {
            acc[0][j] *= a0; acc[1][j] *= a1; acc[2][j] *= a2; acc[3][j] *= a3;
        }
#pragma unroll 8
        for (int kk = 0; kk < 64; kk++) {
            float4 pa = *(const float4*)&Ps[kk][ty * 4];
            float4 vb = *(const float4*)&Vs[kk][tx * 4];
            float pr[4] = {pa.x, pa.y, pa.z, pa.w};
            float vr[4] = {vb.x, vb.y, vb.z, vb.w};
#pragma unroll
            for (int i = 0; i < 4; i++)
#pragma unroll
                for (int j = 0; j < 4; j++)
                    acc[i][j] = fmaf(pr[i], vr[j], acc[i][j]);
        }
    }

    // epilogue: normalize + store y in (b,t,c) layout
#pragma unroll
    for (int i = 0; i < 4; i++) {
        float inv = 1.f / lrow[ty * 4 + i];
        float4 ov;
        ov.x = acc[i][0] * inv; ov.y = acc[i][1] * inv;
        ov.z = acc[i][2] * inv; ov.w = acc[i][3] * inv;
        *(float4*)(Yg + base + (size_t)(q0 + ty * 4 + i) * CH + tx * 4) = ov;
    }
}

// ---------------- orchestration ----------------
extern "C" void kernel_launch(void* const* d_in, const int* in_sizes, int n_in,
                              void* d_out, int out_size)
{
    const float* img  = (const float*)d_in[0];
    const float* rad  = (const float*)d_in[1];
    const float* pos  = (const float*)d_in[2];
    const float* ln1w = (const float*)d_in[3];
    const float* ln1b = (const float*)d_in[4];
    const float* Wq   = (const float*)d_in[5];
    const float* bq   = (const float*)d_in[6];
    const float* Wk   = (const float*)d_in[7];
    const float* bk   = (const float*)d_in[8];
    const float* Wv   = (const float*)d_in[9];
    const float* bv   = (const float*)d_in[10];
    const float* Wo   = (const float*)d_in[11];
    const float* bo   = (const float*)d_in[12];
    const float* ln2w = (const float*)d_in[13];
    const float* ln2b = (const float*)d_in[14];
    const float* W1   = (const float*)d_in[15];
    const float* b1   = (const float*)d_in[16];
    const float* W2   = (const float*)d_in[17];
    const float* b2   = (const float*)d_in[18];
    const float* lnfw = (const float*)d_in[19];
    const float* lnfb = (const float*)d_in[20];
    float* out = (float*)d_out;

    float *x, *h, *q, *k, *v, *y, *ff;
    cudaGetSymbolAddress((void**)&x,  g_x);
    cudaGetSymbolAddress((void**)&h,  g_h);
    cudaGetSymbolAddress((void**)&q,  g_q);
    cudaGetSymbolAddress((void**)&k,  g_k);
    cudaGetSymbolAddress((void**)&v,  g_v);
    cudaGetSymbolAddress((void**)&y,  g_y);
    cudaGetSymbolAddress((void**)&ff, g_ff);

    cudaFuncSetAttribute(attn_kernel,
                         cudaFuncAttributeMaxDynamicSharedMemorySize,
                         ATTN_SMEM_BYTES);

    embed_kernel<<<(MROWS * CH) / 256, 256>>>(img, rad, pos);

    for (int l = 0; l < NLAYER; l++) {
        const size_t wcc = (size_t)l * CH * CH;
        const size_t wcf = (size_t)l * CH * FFDIM;

        ln_kernel<<<MROWS / 8, 256>>>(x, h, ln1w + l * CH, ln1b + l * CH);

        gemm_kernel<0, false><<<dim3(CH / 64, MROWS / 64), 256>>>(
            h, Wq + wcc, bq + l * CH, nullptr, q, CH, CH);
        gemm_kernel<0, false><<<dim3(CH / 64, MROWS / 64), 256>>>(
            h, Wk + wcc, bk + l * CH, nullptr, k, CH, CH);
        gemm_kernel<0, false><<<dim3(CH / 64, MROWS / 64), 256>>>(
            h, Wv + wcc, bv + l * CH, nullptr, v, CH, CH);

        attn_kernel<<<dim3(TOK / 64, NHEAD, BATCH), 256, ATTN_SMEM_BYTES>>>(q, k, v, y);

        gemm_kernel<0, true><<<dim3(CH / 64, MROWS / 64), 256>>>(
            y, Wo + wcc, bo + l * CH, x, x, CH, CH);

        ln_kernel<<<MROWS / 8, 256>>>(x, h, ln2w + l * CH, ln2b + l * CH);

        gemm_kernel<1, false><<<dim3(FFDIM / 64, MROWS / 64), 256>>>(
            h, W1 + wcf, b1 + l * FFDIM, nullptr, ff, FFDIM, CH);

        gemm_kernel<0, true><<<dim3(CH / 64, MROWS / 64), 256>>>(
            ff, W2 + wcf, b2 + l * CH, x, x, CH, FFDIM);
    }

    lnf_kernel<<<MROWS / 8, 256>>>(x, out, lnfw, lnfb);
}

// round 2
// speedup vs baseline: 1.0966x; 1.0966x over previous
#include <cuda_runtime.h>
#include <math.h>

// ---------------- problem constants ----------------
#define BATCH 16
#define TOK   1280
#define CH    512
#define NHEAD 8
#define HDIM  64
#define NLAYER 6
#define FFDIM 2048
#define MROWS (BATCH*TOK)    // 20480

// ---------------- device scratch ----------------
__device__ float g_x [MROWS*CH];
__device__ float g_h [MROWS*CH];
__device__ float g_q [MROWS*CH];
__device__ float g_k [MROWS*CH];
__device__ float g_v [MROWS*CH];
__device__ float g_y [MROWS*CH];
__device__ float g_ff[MROWS*FFDIM];

// ---------------- embed ----------------
__global__ void embed_kernel(const float* __restrict__ img,
                             const float* __restrict__ rad,
                             const float* __restrict__ pos)
{
    int idx = blockIdx.x * blockDim.x + threadIdx.x;
    int c   = idx & (CH - 1);
    int row = idx >> 9;
    int b   = row / TOK;
    int t   = row - b * TOK;
    float v;
    if (t < 1024) v = img[(size_t)(b * CH + c) * 1024 + t];
    else          v = rad[(size_t)(b * CH + c) * 256  + (t - 1024)];
    g_x[idx] = v + pos[t * CH + c];
}

// ---------------- layernorm ----------------
__global__ void ln_kernel(const float* __restrict__ x, float* __restrict__ o,
                          const float* __restrict__ w, const float* __restrict__ bb)
{
    int warp = threadIdx.x >> 5, lane = threadIdx.x & 31;
    int row  = blockIdx.x * 8 + warp;
    const float4* xr = (const float4*)(x + (size_t)row * CH);
    float4 v[4];
    float s = 0.f, s2 = 0.f;
#pragma unroll
    for (int i = 0; i < 4; i++) {
        v[i] = xr[lane + 32 * i];
        s  += v[i].x + v[i].y + v[i].z + v[i].w;
        s2 += v[i].x*v[i].x + v[i].y*v[i].y + v[i].z*v[i].z + v[i].w*v[i].w;
    }
#pragma unroll
    for (int off = 16; off; off >>= 1) {
        s  += __shfl_xor_sync(0xffffffffu, s,  off);
        s2 += __shfl_xor_sync(0xffffffffu, s2, off);
    }
    float m   = s * (1.f / CH);
    float inv = rsqrtf(s2 * (1.f / CH) - m * m + 1e-5f);
    const float4* wr = (const float4*)w;
    const float4* br = (const float4*)bb;
    float4* orow = (float4*)(o + (size_t)row * CH);
#pragma unroll
    for (int i = 0; i < 4; i++) {
        float4 wv = wr[lane + 32 * i], bv = br[lane + 32 * i], ov;
        ov.x = (v[i].x - m) * inv * wv.x + bv.x;
        ov.y = (v[i].y - m) * inv * wv.y + bv.y;
        ov.z = (v[i].z - m) * inv * wv.z + bv.z;
        ov.w = (v[i].w - m) * inv * wv.w + bv.w;
        orow[lane + 32 * i] = ov;
    }
}

// ---------------- final LN + scatter ----------------
__global__ void lnf_kernel(const float* __restrict__ x, float* __restrict__ out,
                           const float* __restrict__ w, const float* __restrict__ bb)
{
    int warp = threadIdx.x >> 5, lane = threadIdx.x & 31;
    int row  = blockIdx.x * 8 + warp;
    const float4* xr = (const float4*)(x + (size_t)row * CH);
    float4 v[4];
    float s = 0.f, s2 = 0.f;
#pragma unroll
    for (int i = 0; i < 4; i++) {
        v[i] = xr[lane + 32 * i];
        s  += v[i].x + v[i].y + v[i].z + v[i].w;
        s2 += v[i].x*v[i].x + v[i].y*v[i].y + v[i].z*v[i].z + v[i].w*v[i].w;
    }
#pragma unroll
    for (int off = 16; off; off >>= 1) {
        s  += __shfl_xor_sync(0xffffffffu, s,  off);
        s2 += __shfl_xor_sync(0xffffffffu, s2, off);
    }
    float m   = s * (1.f / CH);
    float inv = rsqrtf(s2 * (1.f / CH) - m * m + 1e-5f);
    int b = row / TOK, t = row - b * TOK;
    float* dst;
    if (t < 1024) dst = out + ((size_t)b * 1024 + t) * CH;
    else          dst = out + (size_t)BATCH*1024*CH + ((size_t)b*256 + (t-1024))*CH;
    const float4* wr = (const float4*)w;
    const float4* br = (const float4*)bb;
    float4* orow = (float4*)dst;
#pragma unroll
    for (int i = 0; i < 4; i++) {
        float4 wv = wr[lane + 32 * i], bv = br[lane + 32 * i], ov;
        ov.x = (v[i].x - m) * inv * wv.x + bv.x;
        ov.y = (v[i].y - m) * inv * wv.y + bv.y;
        ov.z = (v[i].z - m) * inv * wv.z + bv.z;
        ov.w = (v[i].w - m) * inv * wv.w + bv.w;
        orow[lane + 32 * i] = ov;
    }
}

// ---------------- fp32 GEMM core: 128x128 tile, BK=16, 8x8 microtile ----------------
template<int ACT, bool RES>
__device__ __forceinline__ void gemm_body(
    const float* __restrict__ A, const float* __restrict__ Bm,
    const float* __restrict__ bias, const float* __restrict__ res,
    float* __restrict__ out, int N, int K, int m0, int n0,
    float (*As)[16][128], float (*Bs)[16][128])
{
    const int tid = threadIdx.x;
    const int tx = tid & 15, ty = tid >> 4;

    const int arow = tid >> 1, ak = (tid & 1) * 8;   // A: 128 rows x 16k
    const int brow = ty,       bcol = tx * 8;        // B: 16 rows x 128n

    const float* Aptr = A + (size_t)(m0 + arow) * K + ak;
    const float* Bptr = Bm + (size_t)brow * N + n0 + bcol;

    float4 a0 = *(const float4*)(Aptr);
    float4 a1 = *(const float4*)(Aptr + 4);
    float4 b0 = *(const float4*)(Bptr);
    float4 b1 = *(const float4*)(Bptr + 4);

    float acc[8][8];
#pragma unroll
    for (int i = 0; i < 8; i++)
#pragma unroll
        for (int j = 0; j < 8; j++) acc[i][j] = 0.f;

    // stage 0
    {
        float tmp[8] = {a0.x,a0.y,a0.z,a0.w,a1.x,a1.y,a1.z,a1.w};
#pragma unroll
        for (int t = 0; t < 8; t++) As[0][ak + t][arow] = tmp[t];
        *(float4*)&Bs[0][brow][bcol]     = b0;
        *(float4*)&Bs[0][brow][bcol + 4] = b1;
    }
    __syncthreads();

    int buf = 0;
    for (int k0 = 16; ; k0 += 16) {
        bool more = (k0 < K);
        if (more) {
            a0 = *(const float4*)(Aptr + k0);
            a1 = *(const float4*)(Aptr + k0 + 4);
            b0 = *(const float4*)(Bptr + (size_t)k0 * N);
            b1 = *(const float4*)(Bptr + (size_t)k0 * N + 4);
        }
#pragma unroll
        for (int kk = 0; kk < 16; kk++) {
            float4 af0 = *(const float4*)&As[buf][kk][ty * 8];
            float4 af1 = *(const float4*)&As[buf][kk][ty * 8 + 4];
            float4 bf0 = *(const float4*)&Bs[buf][kk][tx * 8];
            float4 bf1 = *(const float4*)&Bs[buf][kk][tx * 8 + 4];
            float ar[8] = {af0.x,af0.y,af0.z,af0.w,af1.x,af1.y,af1.z,af1.w};
            float br[8] = {bf0.x,bf0.y,bf0.z,bf0.w,bf1.x,bf1.y,bf1.z,bf1.w};
#pragma unroll
            for (int i = 0; i < 8; i++)
#pragma unroll
                for (int j = 0; j < 8; j++)
                    acc[i][j] = fmaf(ar[i], br[j], acc[i][j]);
        }
        if (!more) break;
        {
            float tmp[8] = {a0.x,a0.y,a0.z,a0.w,a1.x,a1.y,a1.z,a1.w};
#pragma unroll
            for (int t = 0; t < 8; t++) As[buf ^ 1][ak + t][arow] = tmp[t];
            *(float4*)&Bs[buf ^ 1][brow][bcol]     = b0;
            *(float4*)&Bs[buf ^ 1][brow][bcol + 4] = b1;
        }
        __syncthreads();
        buf ^= 1;
    }

    float4 bv0 = *(const float4*)(bias + n0 + tx * 8);
    float4 bv1 = *(const float4*)(bias + n0 + tx * 8 + 4);
    float bb[8] = {bv0.x,bv0.y,bv0.z,bv0.w,bv1.x,bv1.y,bv1.z,bv1.w};
#pragma unroll
    for (int i = 0; i < 8; i++) {
        int row = m0 + ty * 8 + i;
        float vv[8];
#pragma unroll
        for (int j = 0; j < 8; j++) {
            vv[j] = acc[i][j] + bb[j];
            if (ACT == 1) vv[j] = fmaxf(vv[j], 0.f);
        }
        if (RES) {
            float4 r0 = *(const float4*)(res + (size_t)row * N + n0 + tx * 8);
            float4 r1 = *(const float4*)(res + (size_t)row * N + n0 + tx * 8 + 4);
            vv[0]+=r0.x; vv[1]+=r0.y; vv[2]+=r0.z; vv[3]+=r0.w;
            vv[4]+=r1.x; vv[5]+=r1.y; vv[6]+=r1.z; vv[7]+=r1.w;
        }
        float4 o0 = {vv[0],vv[1],vv[2],vv[3]};
        float4 o1 = {vv[4],vv[5],vv[6],vv[7]};
        *(float4*)(out + (size_t)row * N + n0 + tx * 8)     = o0;
        *(float4*)(out + (size_t)row * N + n0 + tx * 8 + 4) = o1;
    }
}

template<int ACT, bool RES>
__global__ void __launch_bounds__(256, 2) gemm128_kernel(
    const float* __restrict__ A, const float* __restrict__ Bm,
    const float* __restrict__ bias, const float* __restrict__ res,
    float* __restrict__ out, int N, int K)
{
    __shared__ float As[2][16][128];
    __shared__ float Bs[2][16][128];
    gemm_body<ACT, RES>(A, Bm, bias, res, out, N, K,
                        blockIdx.y * 128, blockIdx.x * 128, As, Bs);
}

// fused QKV: blockIdx.x in [0,12): matrix = x>>2, n-tile = x&3
__global__ void __launch_bounds__(256, 2) qkv_kernel(
    const float* __restrict__ A,
    const float* __restrict__ B0, const float* __restrict__ B1, const float* __restrict__ B2,
    const float* __restrict__ c0, const float* __restrict__ c1, const float* __restrict__ c2,
    float* __restrict__ o0, float* __restrict__ o1, float* __restrict__ o2)
{
    __shared__ float As[2][16][128];
    __shared__ float Bs[2][16][128];
    int mat = blockIdx.x >> 2;
    const float* Bm   = (mat == 0) ? B0 : (mat == 1) ? B1 : B2;
    const float* bias = (mat == 0) ? c0 : (mat == 1) ? c1 : c2;
    float*       out  = (mat == 0) ? o0 : (mat == 1) ? o1 : o2;
    gemm_body<0, false>(A, Bm, bias, nullptr, out, CH, CH,
                        blockIdx.y * 128, (blockIdx.x & 3) * 128, As, Bs);
}

// ---------------- fused flash attention, register-resident softmax ----------------
#define ATTN_SMEM_FLOATS (4 * 64 * 68)
#define ATTN_SMEM_BYTES  (ATTN_SMEM_FLOATS * 4)

__global__ void __launch_bounds__(256, 3) attn_kernel(
    const float* __restrict__ Qg, const float* __restrict__ Kg,
    const float* __restrict__ Vg, float* __restrict__ Yg)
{
    extern __shared__ float sm[];
    float (*Qs)[68] = (float(*)[68])(sm);               // [d][i]
    float (*Ks)[68] = (float(*)[68])(sm + 64 * 68);     // [d][j]
    float (*Vs)[68] = (float(*)[68])(sm + 2 * 64 * 68); // [kk][j]
    float (*Ps)[68] = (float(*)[68])(sm + 3 * 64 * 68); // [kk][i]

    const int q0 = blockIdx.x * 64;
    const int h  = blockIdx.y;
    const int bz = blockIdx.z;
    const int tid = threadIdx.x;
    const int tx = tid & 15, ty = tid >> 4;
    const size_t base = (size_t)bz * TOK * CH + h * HDIM;

    // load Q tile (transposed, pre-scaled)
    {
        int i = tid >> 2;
#pragma unroll
        for (int rep = 0; rep < 4; rep++) {
            int d0 = (tid & 3) * 4 + rep * 16;
            float4 qv = *(const float4*)(Qg + base + (size_t)(q0 + i) * CH + d0);
            Qs[d0 + 0][i] = qv.x * 0.125f;
            Qs[d0 + 1][i] = qv.y * 0.125f;
            Qs[d0 + 2][i] = qv.z * 0.125f;
            Qs[d0 + 3][i] = qv.w * 0.125f;
        }
    }

    float acc[4][4];
    float mreg[4], lreg[4];
#pragma unroll
    for (int i = 0; i < 4; i++) {
        mreg[i] = -1e30f; lreg[i] = 0.f;
#pragma unroll
        for (int j = 0; j < 4; j++) acc[i][j] = 0.f;
    }

    for (int kt = 0; kt < 20; kt++) {
        __syncthreads();
        int k0 = kt * 64;
        {
            int j = tid >> 2;
#pragma unroll
            for (int rep = 0; rep < 4; rep++) {
                int d0 = (tid & 3) * 4 + rep * 16;
                float4 kv = *(const float4*)(Kg + base + (size_t)(k0 + j) * CH + d0);
                Ks[d0 + 0][j] = kv.x;
                Ks[d0 + 1][j] = kv.y;
                Ks[d0 + 2][j] = kv.z;
                Ks[d0 + 3][j] = kv.w;
                float4 vv = *(const float4*)(Vg + base + (size_t)(k0 + j) * CH + d0);
                *(float4*)&Vs[j][d0] = vv;
            }
        }
        __syncthreads();

        // S = Q @ K^T
        float s[4][4];
#pragma unroll
        for (int i = 0; i < 4; i++)
#pragma unroll
            for (int j = 0; j < 4; j++) s[i][j] = 0.f;
#pragma unroll 8
        for (int d = 0; d < 64; d++) {
            float4 qa = *(const float4*)&Qs[d][ty * 4];
            float4 kb = *(const float4*)&Ks[d][tx * 4];
            float qr[4] = {qa.x, qa.y, qa.z, qa.w};
            float kr[4] = {kb.x, kb.y, kb.z, kb.w};
#pragma unroll
            for (int i = 0; i < 4; i++)
#pragma unroll
                for (int j = 0; j < 4; j++)
                    s[i][j] = fmaf(qr[i], kr[j], s[i][j]);
        }

        // register-resident online softmax (reduce over 16-lane tx group)
        float alpha[4];
#pragma unroll
        for (int i = 0; i < 4; i++) {
            float mloc = fmaxf(fmaxf(s[i][0], s[i][1]), fmaxf(s[i][2], s[i][3]));
#pragma unroll
            for (int off = 8; off; off >>= 1)
                mloc = fmaxf(mloc, __shfl_xor_sync(0xffffffffu, mloc, off));
            float mnew = fmaxf(mreg[i], mloc);
            alpha[i] = __expf(mreg[i] - mnew);
            float ssum = 0.f;
#pragma unroll
            for (int j = 0; j < 4; j++) {
                float p = __expf(s[i][j] - mnew);
                Ps[tx * 4 + j][ty * 4 + i] = p;
                ssum += p;
            }
#pragma unroll
            for (int off = 8; off; off >>= 1)
                ssum += __shfl_xor_sync(0xffffffffu, ssum, off);
            lreg[i] = lreg[i] * alpha[i] + ssum;
            mreg[i] = mnew;
        }
        __syncthreads();

        // O = O*alpha + P @ V
#pragma unroll
        for (int i = 0; i < 4; i++)
#pragma unroll
            for (int j = 0; j < 4; j++) acc[i][j] *= alpha[i];
#pragma unroll 8
        for (int kk = 0; kk < 64; kk++) {
            float4 pa = *(const float4*)&Ps[kk][ty * 4];
            float4 vb = *(const float4*)&Vs[kk][tx * 4];
            float pr[4] = {pa.x, pa.y, pa.z, pa.w};
            float vr[4] = {vb.x, vb.y, vb.z, vb.w};
#pragma unroll
            for (int i = 0; i < 4; i++)
#pragma unroll
                for (int j = 0; j < 4; j++)
                    acc[i][j] = fmaf(pr[i], vr[j], acc[i][j]);
        }
    }

    // epilogue
#pragma unroll
    for (int i = 0; i < 4; i++) {
        float inv = 1.f / lreg[i];
        float4 ov;
        ov.x = acc[i][0] * inv; ov.y = acc[i][1] * inv;
        ov.z = acc[i][2] * inv; ov.w = acc[i][3] * inv;
        *(float4*)(Yg + base + (size_t)(q0 + ty * 4 + i) * CH + tx * 4) = ov;
    }
}

// ---------------- orchestration ----------------
extern "C" void kernel_launch(void* const* d_in, const int* in_sizes, int n_in,
                              void* d_out, int out_size)
{
    const float* img  = (const float*)d_in[0];
    const float* rad  = (const float*)d_in[1];
    const float* pos  = (const float*)d_in[2];
    const float* ln1w = (const float*)d_in[3];
    const float* ln1b = (const float*)d_in[4];
    const float* Wq   = (const float*)d_in[5];
    const float* bq   = (const float*)d_in[6];
    const float* Wk   = (const float*)d_in[7];
    const float* bk   = (const float*)d_in[8];
    const float* Wv   = (const float*)d_in[9];
    const float* bv   = (const float*)d_in[10];
    const float* Wo   = (const float*)d_in[11];
    const float* bo   = (const float*)d_in[12];
    const float* ln2w = (const float*)d_in[13];
    const float* ln2b = (const float*)d_in[14];
    const float* W1   = (const float*)d_in[15];
    const float* b1   = (const float*)d_in[16];
    const float* W2   = (const float*)d_in[17];
    const float* b2   = (const float*)d_in[18];
    const float* lnfw = (const float*)d_in[19];
    const float* lnfb = (const float*)d_in[20];
    float* out = (float*)d_out;

    float *x, *h, *q, *k, *v, *y, *ff;
    cudaGetSymbolAddress((void**)&x,  g_x);
    cudaGetSymbolAddress((void**)&h,  g_h);
    cudaGetSymbolAddress((void**)&q,  g_q);
    cudaGetSymbolAddress((void**)&k,  g_k);
    cudaGetSymbolAddress((void**)&v,  g_v);
    cudaGetSymbolAddress((void**)&y,  g_y);
    cudaGetSymbolAddress((void**)&ff, g_ff);

    cudaFuncSetAttribute(attn_kernel,
                         cudaFuncAttributeMaxDynamicSharedMemorySize,
                         ATTN_SMEM_BYTES);

    embed_kernel<<<(MROWS * CH) / 256, 256>>>(img, rad, pos);

    for (int l = 0; l < NLAYER; l++) {
        const size_t wcc = (size_t)l * CH * CH;
        const size_t wcf = (size_t)l * CH * FFDIM;

        ln_kernel<<<MROWS / 8, 256>>>(x, h, ln1w + l * CH, ln1b + l * CH);

        qkv_kernel<<<dim3(12, MROWS / 128), 256>>>(
            h, Wq + wcc, Wk + wcc, Wv + wcc,
            bq + l * CH, bk + l * CH, bv + l * CH, q, k, v);

        attn_kernel<<<dim3(TOK / 64, NHEAD, BATCH), 256, ATTN_SMEM_BYTES>>>(q, k, v, y);

        gemm128_kernel<0, true><<<dim3(CH / 128, MROWS / 128), 256>>>(
            y, Wo + wcc, bo + l * CH, x, x, CH, CH);

        ln_kernel<<<MROWS / 8, 256>>>(x, h, ln2w + l * CH, ln2b + l * CH);

        gemm128_kernel<1, false><<<dim3(FFDIM / 128, MROWS / 128), 256>>>(
            h, W1 + wcf, b1 + l * FFDIM, nullptr, ff, FFDIM, CH);

        gemm128_kernel<0, true><<<dim3(CH / 128, MROWS / 128), 256>>>(
            ff, W2 + wcf, b2 + l * CH, x, x, CH, FFDIM);
    }

    lnf_kernel<<<MROWS / 8, 256>>>(x, out, lnfw, lnfb);
}